// round 7
// baseline (speedup 1.0000x reference)
#include <cuda_runtime.h>
#include <cstdint>

#define MARGIN 0.1f
#define TPB 256
#define VPT 2           // float4 vectors per thread: TPB*VPT*4 = 2048 = L
#define EPT (VPT * 4)

// Global accumulators. Zero at module load; hinge_final_kernel resets them to
// zero after each launch, so every invocation (correctness call, capture call,
// each graph replay) observes identical initial state.
__device__ float g_total;
__device__ float g_count;

__global__ void __launch_bounds__(TPB) hinge_row_kernel(
    const float* __restrict__ scores,
    const int* __restrict__ lens,
    const int* __restrict__ labels,
    int L)
{
    const int row = blockIdx.x;
    const int len = lens[row];          // uniform across CTA -> scalar branch
    const size_t base = (size_t)row * (size_t)L;
    const float4* __restrict__ srow = (const float4*)(scores + base);
    const int4*   __restrict__ lrow = (const int4*)(labels + base);
    const int t = threadIdx.x;
    const int L4 = L >> 2;

    float s[EPT];
    bool isNeg[EPT];

    float pos_sum = 0.0f;
    int pos_cnt = 0;

#pragma unroll
    for (int k = 0; k < VPT; k++) {
        const int v = t + k * TPB;
        const int j0 = v << 2;
        float4 sv = make_float4(0.f, 0.f, 0.f, 0.f);
        int4   lv = make_int4(-1, -1, -1, -1);
        // Only touch memory the math uses: elements with j >= len are dead.
        // (Partial vector at the len boundary is safe: row storage extends to L.)
        if (v < L4 && j0 < len) {
            sv = srow[v];
            lv = lrow[v];
        }
        const float se[4] = { sv.x, sv.y, sv.z, sv.w };
        const int   le[4] = { lv.x, lv.y, lv.z, lv.w };
#pragma unroll
        for (int e = 0; e < 4; e++) {
            const int j = j0 + e;
            const bool valid = (j < L) && (j < len);
            const bool p = valid && (le[e] == 1);
            const bool n = valid && (le[e] == 0);
            s[k * 4 + e] = se[e];
            isNeg[k * 4 + e] = n;
            if (p) { pos_sum += se[e]; pos_cnt++; }
        }
    }

    // ---- block reduce pos_sum / pos_cnt ----
    __shared__ float sh_f[TPB / 32];
    __shared__ int   sh_i[TPB / 32];
    __shared__ float shh_f[TPB / 32];
    __shared__ int   shh_i[TPB / 32];
    __shared__ float sh_chosen;

#pragma unroll
    for (int o = 16; o > 0; o >>= 1) {
        pos_sum += __shfl_down_sync(0xFFFFFFFFu, pos_sum, o);
        pos_cnt += __shfl_down_sync(0xFFFFFFFFu, pos_cnt, o);
    }
    const int wid = t >> 5, lid = t & 31;
    if (lid == 0) { sh_f[wid] = pos_sum; sh_i[wid] = pos_cnt; }
    __syncthreads();
    if (t == 0) {
        float ps = 0.0f; int pc = 0;
#pragma unroll
        for (int w = 0; w < TPB / 32; w++) { ps += sh_f[w]; pc += sh_i[w]; }
        sh_chosen = (pc > 0) ? ps : -MARGIN;
    }
    __syncthreads();
    const float chosen = sh_chosen;

    // ---- hinge over negatives, from register-resident scores ----
    float hs = 0.0f;
    int nc = 0;
#pragma unroll
    for (int k = 0; k < EPT; k++) {
        if (isNeg[k]) {
            hs += fmaxf(MARGIN + s[k] - chosen, 0.0f);
            nc++;
        }
    }
#pragma unroll
    for (int o = 16; o > 0; o >>= 1) {
        hs += __shfl_down_sync(0xFFFFFFFFu, hs, o);
        nc += __shfl_down_sync(0xFFFFFFFFu, nc, o);
    }
    if (lid == 0) { shh_f[wid] = hs; shh_i[wid] = nc; }
    __syncthreads();
    if (t == 0) {
        float h = 0.0f; int n = 0;
#pragma unroll
        for (int w = 0; w < TPB / 32; w++) { h += shh_f[w]; n += shh_i[w]; }
        if (len > 0 && n > 0) {              // valid_obs = (len>0) & has_neg
            atomicAdd(&g_total, h / (float)n);
            atomicAdd(&g_count, 1.0f);
        }
    }
}

__global__ void hinge_final_kernel(float* __restrict__ out)
{
    const float T = g_total;
    const float C = g_count;
    out[0] = (C > 0.0f) ? (T / fmaxf(C, 1.0f)) : 0.0f;
    // Reset for the next launch / graph replay.
    g_total = 0.0f;
    g_count = 0.0f;
}

extern "C" void kernel_launch(void* const* d_in, const int* in_sizes, int n_in,
                              void* d_out, int out_size)
{
    const float* scores = (const float*)d_in[0];
    const int*   lens   = (const int*)d_in[1];
    const int*   labels = (const int*)d_in[2];
    float* out = (float*)d_out;

    const int B = in_sizes[1];            // candidate_lengths element count
    const int L = in_sizes[0] / B;        // 2048

    hinge_row_kernel<<<B, TPB>>>(scores, lens, labels, L);
    hinge_final_kernel<<<1, 1>>>(out);
}

// round 8
// speedup vs baseline: 1.2939x; 1.2939x over previous
#include <cuda_runtime.h>
#include <cstdint>

#define MARGIN 0.1f
#define TPB 256
#define LMAX 2048
#define NWARP (TPB / 32)

// Global accumulators. Zero at module load; hinge_final_kernel resets them to
// zero after each launch, so every invocation (correctness call, capture call,
// each graph replay) observes identical initial state.
__device__ float g_total;
__device__ float g_count;

__global__ void __launch_bounds__(TPB) hinge_row_kernel(
    const float* __restrict__ scores,
    const int* __restrict__ lens,
    const int* __restrict__ labels,
    int L)
{
    const int row = blockIdx.x;
    const int len = lens[row];               // uniform across CTA
    const size_t base = (size_t)row * (size_t)L;
    const float4* __restrict__ srow = (const float4*)(scores + base);
    const int4*   __restrict__ lrow = (const int4*)(labels + base);
    const int t = threadIdx.x;
    const int L4 = L >> 2;
    const int lenc = (len < L) ? len : L;
    const int nv = (lenc + 3) >> 2;          // float4 vectors actually needed
    const int lim = nv << 2;                 // staged element count (multiple of 4)

    // Staged scores: s if element is a valid negative, else -1e30 (hinge -> 0).
    __shared__ float4 s_sm4[LMAX / 4];       // 8 KB
    __shared__ float sh_f[NWARP];
    __shared__ int   sh_i[NWARP];
    __shared__ int   sh_n[NWARP];
    __shared__ float shh_f[NWARP];
    __shared__ float sh_chosen;

    float pos_sum = 0.0f;
    int pos_cnt = 0;
    int neg_cnt = 0;

    // ---- pass 1: compact, coalesced load of exactly the live prefix ----
    for (int v = t; v < nv; v += TPB) {
        const float4 sv = srow[v];
        const int4   lv = lrow[v];
        const int j0 = v << 2;
        const float se[4] = { sv.x, sv.y, sv.z, sv.w };
        const int   le[4] = { lv.x, lv.y, lv.z, lv.w };
        float st[4];
#pragma unroll
        for (int e = 0; e < 4; e++) {
            const int j = j0 + e;
            const bool valid = (j < lenc);
            const bool p = valid && (le[e] == 1);
            const bool n = valid && (le[e] == 0);
            if (p) { pos_sum += se[e]; pos_cnt++; }
            neg_cnt += n;
            st[e] = n ? se[e] : -1e30f;
        }
        s_sm4[v] = make_float4(st[0], st[1], st[2], st[3]);  // STS.128, conflict-free
    }

    // ---- block reduce pos_sum / pos_cnt / neg_cnt ----
#pragma unroll
    for (int o = 16; o > 0; o >>= 1) {
        pos_sum += __shfl_down_sync(0xFFFFFFFFu, pos_sum, o);
        pos_cnt += __shfl_down_sync(0xFFFFFFFFu, pos_cnt, o);
        neg_cnt += __shfl_down_sync(0xFFFFFFFFu, neg_cnt, o);
    }
    const int wid = t >> 5, lid = t & 31;
    if (lid == 0) { sh_f[wid] = pos_sum; sh_i[wid] = pos_cnt; sh_n[wid] = neg_cnt; }
    __syncthreads();                          // also publishes s_sm4
    int n_total;
    if (t == 0) {
        float ps = 0.0f; int pc = 0; int ng = 0;
#pragma unroll
        for (int w = 0; w < NWARP; w++) { ps += sh_f[w]; pc += sh_i[w]; ng += sh_n[w]; }
        sh_chosen = (pc > 0) ? ps : -MARGIN;
        sh_i[0] = ng;                         // reuse slot to broadcast neg total
    }
    __syncthreads();
    const float chosen = sh_chosen;
    n_total = sh_i[0];

    // ---- pass 2: hinge over staged smem (sentinels contribute 0) ----
    const float* __restrict__ s_sm = (const float*)s_sm4;
    float hs = 0.0f;
    for (int j = t; j < lim; j += TPB)
        hs += fmaxf(MARGIN + s_sm[j] - chosen, 0.0f);

#pragma unroll
    for (int o = 16; o > 0; o >>= 1)
        hs += __shfl_down_sync(0xFFFFFFFFu, hs, o);
    if (lid == 0) shh_f[wid] = hs;
    __syncthreads();
    if (t == 0) {
        float h = 0.0f;
#pragma unroll
        for (int w = 0; w < NWARP; w++) h += shh_f[w];
        if (len > 0 && n_total > 0) {         // valid_obs = (len>0) & has_neg
            atomicAdd(&g_total, h / (float)n_total);
            atomicAdd(&g_count, 1.0f);
        }
    }
}

__global__ void hinge_final_kernel(float* __restrict__ out)
{
    const float T = g_total;
    const float C = g_count;
    out[0] = (C > 0.0f) ? (T / fmaxf(C, 1.0f)) : 0.0f;
    // Reset for the next launch / graph replay.
    g_total = 0.0f;
    g_count = 0.0f;
}

extern "C" void kernel_launch(void* const* d_in, const int* in_sizes, int n_in,
                              void* d_out, int out_size)
{
    const float* scores = (const float*)d_in[0];
    const int*   lens   = (const int*)d_in[1];
    const int*   labels = (const int*)d_in[2];
    float* out = (float*)d_out;

    const int B = in_sizes[1];            // candidate_lengths element count
    const int L = in_sizes[0] / B;        // 2048

    hinge_row_kernel<<<B, TPB>>>(scores, lens, labels, L);
    hinge_final_kernel<<<1, 1>>>(out);
}

// round 9
// speedup vs baseline: 1.6053x; 1.2406x over previous
#include <cuda_runtime.h>
#include <cstdint>

#define MARGIN 0.1f
#define TPB 256
#define WPB (TPB / 32)   // warps (rows) per CTA

// Global accumulators. Zero at module load; hinge_final_kernel resets them to
// zero after each launch, so every invocation (correctness call, capture call,
// each graph replay) observes identical initial state.
__device__ float g_total;
__device__ float g_count;

__global__ void __launch_bounds__(TPB) hinge_row_kernel(
    const float* __restrict__ scores,
    const int* __restrict__ lens,
    const int* __restrict__ labels,
    int L, int B)
{
    const int lane = threadIdx.x & 31;
    const int row = blockIdx.x * WPB + (threadIdx.x >> 5);
    if (row >= B) return;

    const int len = lens[row];          // warp-uniform
    if (len <= 0) return;               // no valid observation, contributes 0

    const size_t base = (size_t)row * (size_t)L;
    const float*  __restrict__ srow  = scores + base;
    const float4* __restrict__ srow4 = (const float4*)srow;
    const int4*   __restrict__ lrow4 = (const int4*)(labels + base);
    const int nv = (len + 3) >> 2;      // live float4/int4 prefix

    // ---- pass 1: scan labels for the (at most one) positive; early exit ----
    float pos_sum = 0.0f;
    int   pos_cnt = 0;
    for (int v0 = 0; v0 < nv; v0 += 32) {
        const int v = v0 + lane;
        bool found = false;
        if (v < nv) {
            const int4 lv = lrow4[v];
            const int  le[4] = { lv.x, lv.y, lv.z, lv.w };
            const int  j0 = v << 2;
#pragma unroll
            for (int e = 0; e < 4; e++) {
                const int j = j0 + e;
                if (j < len && le[e] == 1) {
                    pos_sum += srow[j];     // rare predicated gather
                    pos_cnt++;
                    found = true;
                }
            }
        }
        if (__ballot_sync(0xFFFFFFFFu, found)) break;   // ≤1 positive per row
    }
    // butterfly reduce -> every lane holds totals
#pragma unroll
    for (int o = 16; o > 0; o >>= 1) {
        pos_sum += __shfl_xor_sync(0xFFFFFFFFu, pos_sum, o);
        pos_cnt += __shfl_xor_sync(0xFFFFFFFFu, pos_cnt, o);
    }
    const float chosen = (pos_cnt > 0) ? pos_sum : -MARGIN;

    // ---- pass 2: hinge over ALL valid elements (labels not needed:
    //      the positive's hinge is exactly MARGIN, subtracted below) ----
    float hs = 0.0f;
    for (int v = lane; v < nv; v += 32) {
        const float4 sv = srow4[v];
        const float se[4] = { sv.x, sv.y, sv.z, sv.w };
        const int j0 = v << 2;
#pragma unroll
        for (int e = 0; e < 4; e++) {
            if (j0 + e < len)
                hs += fmaxf(MARGIN + se[e] - chosen, 0.0f);
        }
    }
#pragma unroll
    for (int o = 16; o > 0; o >>= 1)
        hs += __shfl_down_sync(0xFFFFFFFFu, hs, o);

    if (lane == 0) {
        const int neg_cnt = len - pos_cnt;       // valid elems minus positives
        if (neg_cnt > 0) {                       // valid_obs = (len>0) & has_neg
            const float hs_neg = hs - MARGIN * (float)pos_cnt;
            atomicAdd(&g_total, hs_neg / (float)neg_cnt);
            atomicAdd(&g_count, 1.0f);
        }
    }
}

__global__ void hinge_final_kernel(float* __restrict__ out)
{
    const float T = g_total;
    const float C = g_count;
    out[0] = (C > 0.0f) ? (T / fmaxf(C, 1.0f)) : 0.0f;
    // Reset for the next launch / graph replay.
    g_total = 0.0f;
    g_count = 0.0f;
}

extern "C" void kernel_launch(void* const* d_in, const int* in_sizes, int n_in,
                              void* d_out, int out_size)
{
    const float* scores = (const float*)d_in[0];
    const int*   lens   = (const int*)d_in[1];
    const int*   labels = (const int*)d_in[2];
    float* out = (float*)d_out;

    const int B = in_sizes[1];            // candidate_lengths element count
    const int L = in_sizes[0] / B;        // 2048

    const int nblk = (B + WPB - 1) / WPB;
    hinge_row_kernel<<<nblk, TPB>>>(scores, lens, labels, L, B);
    hinge_final_kernel<<<1, 1>>>(out);
}